// round 16
// baseline (speedup 1.0000x reference)
#include <cuda_runtime.h>

#define N_L    8192
#define N_H    32768
#define FDIM   128
#define KSEL   32

#define GRID   32
#define NBINS  (GRID * GRID * GRID)
#define GLO    (-6.0f)
#define CS     0.375f
#define HALF   (0.5f * CS)
#define CSINV  2.6666667f
#define FULLM  0xffffffffu
#define LOGCAP 192
#define SEL_TPB 128

// ---------------- static device scratch (allocation-free) ----------------
__device__ float4 g_slp4[N_L];            // sorted sources (x,y,z,|l|^2)
__device__ float4 g_th4[N_H];             // sorted targets (x,y,z,|h|^2)
__device__ float4 g_xs4[N_L * (FDIM/4)];  // x rows permuted to sorted source order
__device__ int    g_thist[NBINS], g_tcur[NBINS];
__device__ int    g_shist[NBINS], g_scur[NBINS];
__device__ int    g_scell[NBINS];         // start | (count<<16)
__device__ int    g_tbin[N_H], g_sbin[N_L], g_spos[N_L], g_order[N_H];
__device__ float2 g_log[N_H * LOGCAP];    // warp-interleaved insert-event log

// ---------------- prep kernels ----------------
__global__ void zero_kernel() {
    int i = blockIdx.x * blockDim.x + threadIdx.x;
    if (i < NBINS) { g_thist[i] = 0; g_shist[i] = 0; }
}

__device__ __forceinline__ int cellc(float v) {
    int c = (int)((v - GLO) * CSINV);
    return min(max(c, 0), GRID - 1);
}
__device__ __forceinline__ int cellof(float v) {
    int c = (int)floorf((v - GLO) * CSINV);
    return min(max(c, 0), GRID - 1);
}

__device__ __forceinline__ int spread5(int b) {
    return (b & 1) | ((b & 2) << 2) | ((b & 4) << 4) | ((b & 8) << 6) | ((b & 16) << 8);
}

// Fused binning: thread i bins target i (Morton) and, if i < N_L, source i (linear).
__global__ void bin_kernel(const float* __restrict__ pos_h,
                           const float* __restrict__ pos_l) {
    int i = blockIdx.x * blockDim.x + threadIdx.x;
    if (i < N_H) {
        int cx = cellc(pos_h[3*i+0]);
        int cy = cellc(pos_h[3*i+1]);
        int cz = cellc(pos_h[3*i+2]);
        int m = spread5(cx) | (spread5(cy) << 1) | (spread5(cz) << 2);
        g_tbin[i] = m;
        atomicAdd(&g_thist[m], 1);
    }
    if (i < N_L) {
        int cx = cellc(pos_l[3*i+0]);
        int cy = cellc(pos_l[3*i+1]);
        int cz = cellc(pos_l[3*i+2]);
        int b = (cz << 10) | (cy << 5) | cx;
        g_sbin[i] = b;
        atomicAdd(&g_shist[b], 1);
    }
}

// Exclusive prefix over 32768 bins, int4-vectorized. block 0: targets,
// block 1: sources (also emits packed g_scell = start | count<<16).
__global__ void prefix32k_kernel() {
    int sel = blockIdx.x;
    const int* __restrict__ hist = sel ? g_shist : g_thist;
    int* cursor = sel ? g_scur : g_tcur;

    __shared__ int s_part[1024];
    int t = threadIdx.x;
    int base = t * 32;
    const int4* h4 = (const int4*)(hist + base);
    int4 v[8];
    int sum = 0;
#pragma unroll
    for (int j = 0; j < 8; j++) {
        v[j] = h4[j];
        sum += v[j].x + v[j].y + v[j].z + v[j].w;
    }
    s_part[t] = sum;
    __syncthreads();
    for (int d = 1; d < 1024; d <<= 1) {
        int add = (t >= d) ? s_part[t - d] : 0;
        __syncthreads();
        s_part[t] += add;
        __syncthreads();
    }
    int run = t ? s_part[t - 1] : 0;
#pragma unroll
    for (int j = 0; j < 8; j++) {
        int4 c;
        c.x = run; run += v[j].x;
        c.y = run; run += v[j].y;
        c.z = run; run += v[j].z;
        c.w = run; run += v[j].w;
        ((int4*)(cursor + base))[j] = c;
        if (sel) {
            int4 sc;
            sc.x = c.x | (v[j].x << 16);
            sc.y = c.y | (v[j].y << 16);
            sc.z = c.z | (v[j].z << 16);
            sc.w = c.w | (v[j].w << 16);
            ((int4*)(g_scell + base))[j] = sc;
        }
    }
}

// Fused scatter: thread i places target i and, if i < N_L, source i.
__global__ void scatter_kernel(const float* __restrict__ pos_h,
                               const float* __restrict__ pos_l) {
    int i = blockIdx.x * blockDim.x + threadIdx.x;
    if (i < N_H) {
        float x = pos_h[3*i+0], y = pos_h[3*i+1], z = pos_h[3*i+2];
        int p = atomicAdd(&g_tcur[g_tbin[i]], 1);
        g_order[p] = i;
        g_th4[p] = make_float4(x, y, z, fmaf(x, x, fmaf(y, y, z * z)));
    }
    if (i < N_L) {
        float x = pos_l[3*i+0], y = pos_l[3*i+1], z = pos_l[3*i+2];
        int p = atomicAdd(&g_scur[g_sbin[i]], 1);
        g_spos[i] = p;
        g_slp4[p] = make_float4(x, y, z, fmaf(x, x, fmaf(y, y, z * z)));
    }
}

__global__ void xcopy_kernel(const float* __restrict__ x) {
    int i = blockIdx.x * 8 + (threadIdx.x >> 5);
    int c = threadIdx.x & 31;
    const float4* __restrict__ x4 = (const float4*)x;
    g_xs4[g_spos[i] * (FDIM/4) + c] = x4[i * (FDIM/4) + c];
}

// ---------------- fused select+gather kernel ----------------
__device__ __forceinline__ float cand_s(float hx, float hy, float hz, float4 p) {
    float dot = fmaf(hx, p.x, fmaf(hy, p.y, hz * p.z));
    return fmaf(-2.0f, dot, p.w);
}

__device__ __forceinline__ void insert32(float (&q)[KSEL], float s) {
    float cur = s;
#pragma unroll
    for (int j = 0; j < KSEL; j++) {
        float lo = fminf(q[j], cur);
        cur = fmaxf(q[j], cur);
        q[j] = lo;
    }
}

__device__ __forceinline__ float mindc(float h, int g) {
    return fmaxf(fabsf(h - (GLO + (g + 0.5f) * CS)) - HALF, 0.0f);
}

// Insert + append (s, j) to the warp-interleaved event log.
#define INS_LOG(SV, JV)                                                \
    do {                                                               \
        insert32(q, (SV));                                             \
        if (logcnt < LOGCAP) g_log[lb + logcnt * 32] =                 \
            make_float2((SV), __int_as_float(JV));                     \
        logcnt++;                                                      \
    } while (0)

__global__ __launch_bounds__(SEL_TPB) void select_kernel(float* __restrict__ out) {
    __shared__ int   s_ki[SEL_TPB * KSEL];   // winners: indices (16KB)
    __shared__ float s_kw[SEL_TPB * KSEL];   // winners: weights (16KB)
    __shared__ float s_wsum[SEL_TPB];
    __shared__ int   s_o[SEL_TPB];

    const int tid = threadIdx.x;
    const int p = blockIdx.x * SEL_TPB + tid;   // one thread = one target

    const float4 th = g_th4[p];
    const float hx = th.x, hy = th.y, hz = th.z, h2 = th.w;
    s_o[tid] = g_order[p];

    const int cx = cellc(hx), cy = cellc(hy), cz = cellc(hz);
    const float e = fmaxf(fabsf(hx - (GLO + (cx + 0.5f) * CS)),
                    fmaxf(fabsf(hy - (GLO + (cy + 0.5f) * CS)),
                          fabsf(hz - (GLO + (cz + 0.5f) * CS))));

    // ---- Count-prepass: smallest cube (Chebyshev radius cc) holding >= 32 ----
    int cc = 0;
    for (; cc < GRID; ++cc) {
        int zlo = max(cz - cc, 0), zhi = min(cz + cc, GRID - 1);
        int ylo = max(cy - cc, 0), yhi = min(cy + cc, GRID - 1);
        int xlo = max(cx - cc, 0), xhi = min(cx + cc, GRID - 1);
        int total = 0;
        for (int gz = zlo; gz <= zhi; ++gz)
            for (int gy = ylo; gy <= yhi; ++gy) {
                int rowb = (gz << 10) | (gy << 5);
                int sc0 = g_scell[rowb | xlo];
                int sc1 = g_scell[rowb | xhi];
                total += (sc1 & 0xffff) + (sc1 >> 16) - (sc0 & 0xffff);
            }
        if (total >= KSEL) break;
    }
    const float reach = (cc + 0.5f) * CS + e;
    const float thr0 = 3.0f * reach * reach;   // valid upper bound on 32nd d2

    float q[KSEL];
#pragma unroll
    for (int j = 0; j < KSEL; j++) q[j] = __int_as_float(0x7f800000);

    int logcnt = 0;
    const int lb = (p >> 5) * (LOGCAP * 32) + (p & 31);

    // ---- Single pass: rows near-to-far, analytic x-span, exact bubble + log ----
    {
        int zdone = 0;
        for (int iz = 0; iz < 2 * GRID && zdone != 3; ++iz) {
            int dz = (iz & 1) ? ((iz >> 1) + 1) : -(iz >> 1);
            if (iz && ((dz < 0 && (zdone & 1)) || (dz > 0 && (zdone & 2)))) continue;
            int gz = cz + dz;
            if ((unsigned)gz >= GRID) { zdone |= (dz < 0) ? 1 : 2; continue; }
            float mz = mindc(hz, gz);
            float mz2 = mz * mz;
            float thr = fminf(thr0, q[KSEL - 1] + h2);
            if (mz2 > thr) { if (dz) zdone |= (dz < 0) ? 1 : 2; continue; }

            int ydone = 0;
            for (int iy = 0; iy < 2 * GRID && ydone != 3; ++iy) {
                int dy = (iy & 1) ? ((iy >> 1) + 1) : -(iy >> 1);
                if (iy && ((dy < 0 && (ydone & 1)) || (dy > 0 && (ydone & 2)))) continue;
                int gy = cy + dy;
                if ((unsigned)gy >= GRID) { ydone |= (dy < 0) ? 1 : 2; continue; }
                float my = mindc(hy, gy);
                thr = fminf(thr0, q[KSEL - 1] + h2);
                float rem = thr - mz2 - my * my;
                if (rem < 0.0f) { if (dy) ydone |= (dy < 0) ? 1 : 2; continue; }

                float halfw = sqrtf(rem);
                int gx0 = cellof(hx - halfw);
                int gx1 = cellof(hx + halfw);
                int rowb = (gz << 10) | (gy << 5);
                int sc0 = g_scell[rowb | gx0];
                int sc1 = g_scell[rowb | gx1];
                int j  = sc0 & 0xffff;
                int j1 = (sc1 & 0xffff) + (sc1 >> 16);

                for (; j + 4 <= j1; j += 4) {
                    float4 p0 = g_slp4[j + 0];
                    float4 p1 = g_slp4[j + 1];
                    float4 p2 = g_slp4[j + 2];
                    float4 p3 = g_slp4[j + 3];
                    float s0 = cand_s(hx, hy, hz, p0);
                    float s1 = cand_s(hx, hy, hz, p1);
                    float s2 = cand_s(hx, hy, hz, p2);
                    float s3 = cand_s(hx, hy, hz, p3);
                    float m = fminf(fminf(s0, s1), fminf(s2, s3));
                    if (m < q[KSEL - 1]) {
                        if (s0 < q[KSEL - 1]) INS_LOG(s0, j + 0);
                        if (s1 < q[KSEL - 1]) INS_LOG(s1, j + 1);
                        if (s2 < q[KSEL - 1]) INS_LOG(s2, j + 2);
                        if (s3 < q[KSEL - 1]) INS_LOG(s3, j + 3);
                    }
                }
                for (; j < j1; ++j) {
                    float s = cand_s(hx, hy, hz, g_slp4[j]);
                    if (s < q[KSEL - 1]) INS_LOG(s, j);
                }
            }
        }
    }

    const float T = q[KSEL - 1];
    int cnt = 0;
    float wsum = 0.0f;
    const int sb = tid * KSEL;

    if (logcnt <= LOGCAP) {
        // ---- Recover winners from the event log (exact compare on stored s) ----
#pragma unroll 1
        for (int i = 0; i < logcnt; ++i) {
            float2 en = g_log[lb + i * 32];
            if (en.x <= T && cnt < KSEL) {
                float wg = 1.0f / fmaxf(en.x + h2, 1e-16f);
                s_ki[sb + cnt] = __float_as_int(en.y);
                s_kw[sb + cnt] = wg;
                wsum += wg;
                cnt++;
            }
        }
    } else {
        // ---- Rare overflow fallback: exact row-walk rescan (same fmaf chain) ----
        const float thrF = T + h2;
        float wz = sqrtf(fmaxf(thrF, 0.0f));
        int z0 = cellof(hz - wz), z1 = cellof(hz + wz);
        for (int gz = z0; gz <= z1; ++gz) {
            float mz = mindc(hz, gz);
            float remz = thrF - mz * mz;
            if (remz < 0.0f) continue;
            float wy = sqrtf(remz);
            int y0 = cellof(hy - wy), y1 = cellof(hy + wy);
            for (int gy = y0; gy <= y1; ++gy) {
                float my = mindc(hy, gy);
                float rem = remz - my * my;
                if (rem < 0.0f) continue;
                float halfw = sqrtf(rem);
                int gx0 = cellof(hx - halfw);
                int gx1 = cellof(hx + halfw);
                int rowb = (gz << 10) | (gy << 5);
                int sc0 = g_scell[rowb | gx0];
                int sc1 = g_scell[rowb | gx1];
                int j  = sc0 & 0xffff;
                int j1 = (sc1 & 0xffff) + (sc1 >> 16);
                for (; j < j1; ++j) {
                    float s = cand_s(hx, hy, hz, g_slp4[j]);
                    if (s <= T && cnt < KSEL) {
                        float wg = 1.0f / fmaxf(s + h2, 1e-16f);
                        s_ki[sb + cnt] = j;
                        s_kw[sb + cnt] = wg;
                        wsum += wg;
                        cnt++;
                    }
                }
            }
        }
    }
    while (cnt < KSEL) { s_ki[sb + cnt] = 0; s_kw[sb + cnt] = 0.0f; cnt++; }
    s_wsum[tid] = wsum;

    // ---- Fused gather: each warp streams features for its own 32 targets ----
    __syncwarp();
    const int lane = tid & 31;
    const int wbase = tid & ~31;            // warp's first thread in block
    float4* __restrict__ out4 = (float4*)out;

#pragma unroll 1
    for (int lt = wbase; lt < wbase + 32; ++lt) {
        const int b = lt * KSEL;
        float4 acc = make_float4(0.f, 0.f, 0.f, 0.f);
#pragma unroll 4
        for (int k = 0; k < KSEL; k++) {
            int   id = s_ki[b + k];          // broadcast read (all lanes same addr)
            float wk = s_kw[b + k];
            float4 v = g_xs4[id * (FDIM/4) + lane];
            acc.x = fmaf(wk, v.x, acc.x);
            acc.y = fmaf(wk, v.y, acc.y);
            acc.z = fmaf(wk, v.z, acc.z);
            acc.w = fmaf(wk, v.w, acc.w);
        }
        float inv = 1.0f / s_wsum[lt];
        int o = s_o[lt];
        out4[o * (FDIM/4) + lane] =
            make_float4(acc.x * inv, acc.y * inv, acc.z * inv, acc.w * inv);
    }
}

extern "C" void kernel_launch(void* const* d_in, const int* in_sizes, int n_in,
                              void* d_out, int out_size) {
    const float* x     = (const float*)d_in[0];
    const float* pos_l = (const float*)d_in[1];
    const float* pos_h = (const float*)d_in[2];
    float* out = (float*)d_out;

    zero_kernel<<<NBINS / 256, 256>>>();
    bin_kernel<<<N_H / 256, 256>>>(pos_h, pos_l);
    prefix32k_kernel<<<2, 1024>>>();
    scatter_kernel<<<N_H / 256, 256>>>(pos_h, pos_l);
    xcopy_kernel<<<N_L / 8, 256>>>(x);
    select_kernel<<<N_H / SEL_TPB, SEL_TPB>>>(out);
}

// round 17
// speedup vs baseline: 1.3676x; 1.3676x over previous
#include <cuda_runtime.h>

#define N_L    8192
#define N_H    32768
#define FDIM   128
#define KSEL   32

#define GRID   32
#define NBINS  (GRID * GRID * GRID)
#define GLO    (-6.0f)
#define CS     0.375f
#define HALF   (0.5f * CS)
#define CSINV  2.6666667f
#define FULLM  0xffffffffu
#define LOGCAP 192
#define SEL_TPB 128

// ---------------- static device scratch (allocation-free) ----------------
__device__ float4 g_slp4[N_L];            // sorted sources (x,y,z,|l|^2)
__device__ float4 g_th4[N_H];             // sorted targets (x,y,z,|h|^2)
__device__ float4 g_xs4[N_L * (FDIM/4)];  // x rows permuted to sorted source order
__device__ int    g_thist[NBINS], g_tcur[NBINS];
__device__ int    g_shist[NBINS], g_scur[NBINS];
__device__ int    g_scell[NBINS];         // start | (count<<16)
__device__ int    g_tbin[N_H], g_sbin[N_L], g_spos[N_L], g_order[N_H];
__device__ float2 g_log[N_H * LOGCAP];    // warp-interleaved insert-event log
__device__ int    g_tki[N_H * KSEL];
__device__ float  g_tkw[N_H * KSEL];
__device__ float  g_twsum[N_H];

// ---------------- prep kernels ----------------
__global__ void zero_kernel() {
    int i = blockIdx.x * blockDim.x + threadIdx.x;
    if (i < NBINS) { g_thist[i] = 0; g_shist[i] = 0; }
}

__device__ __forceinline__ int cellc(float v) {
    int c = (int)((v - GLO) * CSINV);
    return min(max(c, 0), GRID - 1);
}
__device__ __forceinline__ int cellof(float v) {
    int c = (int)floorf((v - GLO) * CSINV);
    return min(max(c, 0), GRID - 1);
}

__device__ __forceinline__ int spread5(int b) {
    return (b & 1) | ((b & 2) << 2) | ((b & 4) << 4) | ((b & 8) << 6) | ((b & 16) << 8);
}

// Fused binning: thread i bins target i (Morton) and, if i < N_L, source i (linear).
__global__ void bin_kernel(const float* __restrict__ pos_h,
                           const float* __restrict__ pos_l) {
    int i = blockIdx.x * blockDim.x + threadIdx.x;
    if (i < N_H) {
        int cx = cellc(pos_h[3*i+0]);
        int cy = cellc(pos_h[3*i+1]);
        int cz = cellc(pos_h[3*i+2]);
        int m = spread5(cx) | (spread5(cy) << 1) | (spread5(cz) << 2);
        g_tbin[i] = m;
        atomicAdd(&g_thist[m], 1);
    }
    if (i < N_L) {
        int cx = cellc(pos_l[3*i+0]);
        int cy = cellc(pos_l[3*i+1]);
        int cz = cellc(pos_l[3*i+2]);
        int b = (cz << 10) | (cy << 5) | cx;
        g_sbin[i] = b;
        atomicAdd(&g_shist[b], 1);
    }
}

// Exclusive prefix over 32768 bins: shfl warp-scan two-level (2 barriers only).
// block 0: targets; block 1: sources (also emits packed g_scell).
__global__ void prefix32k_kernel() {
    int sel = blockIdx.x;
    const int* __restrict__ hist = sel ? g_shist : g_thist;
    int* cursor = sel ? g_scur : g_tcur;

    __shared__ int s_wtot[32];
    int t = threadIdx.x;
    int lane = t & 31, wid = t >> 5;
    int base = t * 32;
    const int4* h4 = (const int4*)(hist + base);
    int4 v[8];
    int sum = 0;
#pragma unroll
    for (int j = 0; j < 8; j++) {
        v[j] = h4[j];
        sum += v[j].x + v[j].y + v[j].z + v[j].w;
    }
    // inclusive warp scan of per-thread sums
    int inc = sum;
#pragma unroll
    for (int d = 1; d < 32; d <<= 1) {
        int n = __shfl_up_sync(FULLM, inc, d);
        if (lane >= d) inc += n;
    }
    if (lane == 31) s_wtot[wid] = inc;
    __syncthreads();
    if (wid == 0) {
        int w = s_wtot[lane];
        int wi = w;
#pragma unroll
        for (int d = 1; d < 32; d <<= 1) {
            int n = __shfl_up_sync(FULLM, wi, d);
            if (lane >= d) wi += n;
        }
        s_wtot[lane] = wi - w;   // exclusive warp offsets
    }
    __syncthreads();
    int run = s_wtot[wid] + inc - sum;   // exclusive prefix for this thread
#pragma unroll
    for (int j = 0; j < 8; j++) {
        int4 c;
        c.x = run; run += v[j].x;
        c.y = run; run += v[j].y;
        c.z = run; run += v[j].z;
        c.w = run; run += v[j].w;
        ((int4*)(cursor + base))[j] = c;
        if (sel) {
            int4 sc;
            sc.x = c.x | (v[j].x << 16);
            sc.y = c.y | (v[j].y << 16);
            sc.z = c.z | (v[j].z << 16);
            sc.w = c.w | (v[j].w << 16);
            ((int4*)(g_scell + base))[j] = sc;
        }
    }
}

// Fused scatter: thread i places target i and, if i < N_L, source i.
__global__ void scatter_kernel(const float* __restrict__ pos_h,
                               const float* __restrict__ pos_l) {
    int i = blockIdx.x * blockDim.x + threadIdx.x;
    if (i < N_H) {
        float x = pos_h[3*i+0], y = pos_h[3*i+1], z = pos_h[3*i+2];
        int p = atomicAdd(&g_tcur[g_tbin[i]], 1);
        g_order[p] = i;
        g_th4[p] = make_float4(x, y, z, fmaf(x, x, fmaf(y, y, z * z)));
    }
    if (i < N_L) {
        float x = pos_l[3*i+0], y = pos_l[3*i+1], z = pos_l[3*i+2];
        int p = atomicAdd(&g_scur[g_sbin[i]], 1);
        g_spos[i] = p;
        g_slp4[p] = make_float4(x, y, z, fmaf(x, x, fmaf(y, y, z * z)));
    }
}

__global__ void xcopy_kernel(const float* __restrict__ x) {
    int i = blockIdx.x * 8 + (threadIdx.x >> 5);
    int c = threadIdx.x & 31;
    const float4* __restrict__ x4 = (const float4*)x;
    g_xs4[g_spos[i] * (FDIM/4) + c] = x4[i * (FDIM/4) + c];
}

// ---------------- select kernel ----------------
__device__ __forceinline__ float cand_s(float hx, float hy, float hz, float4 p) {
    float dot = fmaf(hx, p.x, fmaf(hy, p.y, hz * p.z));
    return fmaf(-2.0f, dot, p.w);
}

__device__ __forceinline__ void insert32(float (&q)[KSEL], float s) {
    float cur = s;
#pragma unroll
    for (int j = 0; j < KSEL; j++) {
        float lo = fminf(q[j], cur);
        cur = fmaxf(q[j], cur);
        q[j] = lo;
    }
}

__device__ __forceinline__ float mindc(float h, int g) {
    return fmaxf(fabsf(h - (GLO + (g + 0.5f) * CS)) - HALF, 0.0f);
}

// Insert + append (s, j) to the warp-interleaved event log.
#define INS_LOG(SV, JV)                                                \
    do {                                                               \
        insert32(q, (SV));                                             \
        if (logcnt < LOGCAP) g_log[lb + logcnt * 32] =                 \
            make_float2((SV), __int_as_float(JV));                     \
        logcnt++;                                                      \
    } while (0)

__global__ __launch_bounds__(SEL_TPB) void select_kernel() {
    const int p = blockIdx.x * SEL_TPB + threadIdx.x;   // one thread = one target

    const float4 th = g_th4[p];
    const float hx = th.x, hy = th.y, hz = th.z, h2 = th.w;

    const int cx = cellc(hx), cy = cellc(hy), cz = cellc(hz);
    const float e = fmaxf(fabsf(hx - (GLO + (cx + 0.5f) * CS)),
                    fmaxf(fabsf(hy - (GLO + (cy + 0.5f) * CS)),
                          fabsf(hz - (GLO + (cz + 0.5f) * CS))));

    // ---- Count-prepass: smallest cube (Chebyshev radius cc) holding >= 32 ----
    int cc = 0;
    for (; cc < GRID; ++cc) {
        int zlo = max(cz - cc, 0), zhi = min(cz + cc, GRID - 1);
        int ylo = max(cy - cc, 0), yhi = min(cy + cc, GRID - 1);
        int xlo = max(cx - cc, 0), xhi = min(cx + cc, GRID - 1);
        int total = 0;
        for (int gz = zlo; gz <= zhi; ++gz)
            for (int gy = ylo; gy <= yhi; ++gy) {
                int rowb = (gz << 10) | (gy << 5);
                int sc0 = g_scell[rowb | xlo];
                int sc1 = g_scell[rowb | xhi];
                total += (sc1 & 0xffff) + (sc1 >> 16) - (sc0 & 0xffff);
            }
        if (total >= KSEL) break;
    }
    const float reach = (cc + 0.5f) * CS + e;
    const float thr0 = 3.0f * reach * reach;   // valid upper bound on 32nd d2

    float q[KSEL];
#pragma unroll
    for (int j = 0; j < KSEL; j++) q[j] = __int_as_float(0x7f800000);

    int logcnt = 0;
    const int lb = (p >> 5) * (LOGCAP * 32) + (p & 31);

    // ---- Single pass: rows near-to-far, analytic x-span, exact bubble + log ----
    {
        int zdone = 0;
        for (int iz = 0; iz < 2 * GRID && zdone != 3; ++iz) {
            int dz = (iz & 1) ? ((iz >> 1) + 1) : -(iz >> 1);
            if (iz && ((dz < 0 && (zdone & 1)) || (dz > 0 && (zdone & 2)))) continue;
            int gz = cz + dz;
            if ((unsigned)gz >= GRID) { zdone |= (dz < 0) ? 1 : 2; continue; }
            float mz = mindc(hz, gz);
            float mz2 = mz * mz;
            float thr = fminf(thr0, q[KSEL - 1] + h2);
            if (mz2 > thr) { if (dz) zdone |= (dz < 0) ? 1 : 2; continue; }

            int ydone = 0;
            for (int iy = 0; iy < 2 * GRID && ydone != 3; ++iy) {
                int dy = (iy & 1) ? ((iy >> 1) + 1) : -(iy >> 1);
                if (iy && ((dy < 0 && (ydone & 1)) || (dy > 0 && (ydone & 2)))) continue;
                int gy = cy + dy;
                if ((unsigned)gy >= GRID) { ydone |= (dy < 0) ? 1 : 2; continue; }
                float my = mindc(hy, gy);
                thr = fminf(thr0, q[KSEL - 1] + h2);
                float rem = thr - mz2 - my * my;
                if (rem < 0.0f) { if (dy) ydone |= (dy < 0) ? 1 : 2; continue; }

                float halfw = sqrtf(rem);
                int gx0 = cellof(hx - halfw);
                int gx1 = cellof(hx + halfw);
                int rowb = (gz << 10) | (gy << 5);
                int sc0 = g_scell[rowb | gx0];
                int sc1 = g_scell[rowb | gx1];
                int j  = sc0 & 0xffff;
                int j1 = (sc1 & 0xffff) + (sc1 >> 16);

                for (; j + 4 <= j1; j += 4) {
                    float4 p0 = g_slp4[j + 0];
                    float4 p1 = g_slp4[j + 1];
                    float4 p2 = g_slp4[j + 2];
                    float4 p3 = g_slp4[j + 3];
                    float s0 = cand_s(hx, hy, hz, p0);
                    float s1 = cand_s(hx, hy, hz, p1);
                    float s2 = cand_s(hx, hy, hz, p2);
                    float s3 = cand_s(hx, hy, hz, p3);
                    float m = fminf(fminf(s0, s1), fminf(s2, s3));
                    if (m < q[KSEL - 1]) {
                        if (s0 < q[KSEL - 1]) INS_LOG(s0, j + 0);
                        if (s1 < q[KSEL - 1]) INS_LOG(s1, j + 1);
                        if (s2 < q[KSEL - 1]) INS_LOG(s2, j + 2);
                        if (s3 < q[KSEL - 1]) INS_LOG(s3, j + 3);
                    }
                }
                for (; j < j1; ++j) {
                    float s = cand_s(hx, hy, hz, g_slp4[j]);
                    if (s < q[KSEL - 1]) INS_LOG(s, j);
                }
            }
        }
    }

    const float T = q[KSEL - 1];
    int cnt = 0;
    float wsum = 0.0f;
    const int ob = p * KSEL;

    if (logcnt <= LOGCAP) {
        // ---- Recover winners from the log: 4 independent loads per iter (MLP),
        //      exact compare on stored s, early break once all 32 found. ----
        int i = 0;
        for (; i + 4 <= logcnt && cnt < KSEL; i += 4) {
            float2 e0 = g_log[lb + (i + 0) * 32];
            float2 e1 = g_log[lb + (i + 1) * 32];
            float2 e2 = g_log[lb + (i + 2) * 32];
            float2 e3 = g_log[lb + (i + 3) * 32];
#pragma unroll
            for (int u = 0; u < 4; ++u) {
                float2 en = (u == 0) ? e0 : (u == 1) ? e1 : (u == 2) ? e2 : e3;
                if (en.x <= T && cnt < KSEL) {
                    float wg = 1.0f / fmaxf(en.x + h2, 1e-16f);
                    g_tki[ob + cnt] = __float_as_int(en.y);
                    g_tkw[ob + cnt] = wg;
                    wsum += wg;
                    cnt++;
                }
            }
        }
        for (; i < logcnt && cnt < KSEL; ++i) {
            float2 en = g_log[lb + i * 32];
            if (en.x <= T) {
                float wg = 1.0f / fmaxf(en.x + h2, 1e-16f);
                g_tki[ob + cnt] = __float_as_int(en.y);
                g_tkw[ob + cnt] = wg;
                wsum += wg;
                cnt++;
            }
        }
    } else {
        // ---- Rare overflow fallback: exact row-walk rescan (same fmaf chain) ----
        const float thrF = T + h2;
        float wz = sqrtf(fmaxf(thrF, 0.0f));
        int z0 = cellof(hz - wz), z1 = cellof(hz + wz);
        for (int gz = z0; gz <= z1; ++gz) {
            float mz = mindc(hz, gz);
            float remz = thrF - mz * mz;
            if (remz < 0.0f) continue;
            float wy = sqrtf(remz);
            int y0 = cellof(hy - wy), y1 = cellof(hy + wy);
            for (int gy = y0; gy <= y1; ++gy) {
                float my = mindc(hy, gy);
                float rem = remz - my * my;
                if (rem < 0.0f) continue;
                float halfw = sqrtf(rem);
                int gx0 = cellof(hx - halfw);
                int gx1 = cellof(hx + halfw);
                int rowb = (gz << 10) | (gy << 5);
                int sc0 = g_scell[rowb | gx0];
                int sc1 = g_scell[rowb | gx1];
                int j  = sc0 & 0xffff;
                int j1 = (sc1 & 0xffff) + (sc1 >> 16);
                for (; j < j1; ++j) {
                    float s = cand_s(hx, hy, hz, g_slp4[j]);
                    if (s <= T && cnt < KSEL) {
                        float wg = 1.0f / fmaxf(s + h2, 1e-16f);
                        g_tki[ob + cnt] = j;
                        g_tkw[ob + cnt] = wg;
                        wsum += wg;
                        cnt++;
                    }
                }
            }
        }
    }
    while (cnt < KSEL) { g_tki[ob + cnt] = 0; g_tkw[ob + cnt] = 0.0f; cnt++; }
    g_twsum[p] = wsum;
}

// ---------------- gather kernel: one warp per target (wide grid — keep separate) ----
__global__ __launch_bounds__(256) void gather_kernel(float* __restrict__ out) {
    const int lane = threadIdx.x & 31;
    const int p = blockIdx.x * 8 + (threadIdx.x >> 5);

    int   myid = g_tki[p * KSEL + lane];
    float myw  = g_tkw[p * KSEL + lane];

    float4 acc = make_float4(0.f, 0.f, 0.f, 0.f);
#pragma unroll
    for (int k = 0; k < KSEL; k++) {
        int   id = __shfl_sync(FULLM, myid, k);
        float wk = __shfl_sync(FULLM, myw, k);
        float4 v = g_xs4[id * (FDIM/4) + lane];
        acc.x = fmaf(wk, v.x, acc.x);
        acc.y = fmaf(wk, v.y, acc.y);
        acc.z = fmaf(wk, v.z, acc.z);
        acc.w = fmaf(wk, v.w, acc.w);
    }
    float inv = 1.0f / g_twsum[p];
    int o = g_order[p];
    float4* out4 = (float4*)out;
    out4[o * (FDIM/4) + lane] =
        make_float4(acc.x * inv, acc.y * inv, acc.z * inv, acc.w * inv);
}

extern "C" void kernel_launch(void* const* d_in, const int* in_sizes, int n_in,
                              void* d_out, int out_size) {
    const float* x     = (const float*)d_in[0];
    const float* pos_l = (const float*)d_in[1];
    const float* pos_h = (const float*)d_in[2];
    float* out = (float*)d_out;

    zero_kernel<<<NBINS / 256, 256>>>();
    bin_kernel<<<N_H / 256, 256>>>(pos_h, pos_l);
    prefix32k_kernel<<<2, 1024>>>();
    scatter_kernel<<<N_H / 256, 256>>>(pos_h, pos_l);
    xcopy_kernel<<<N_L / 8, 256>>>(x);
    select_kernel<<<N_H / SEL_TPB, SEL_TPB>>>();
    gather_kernel<<<N_H / 8, 256>>>(out);
}